// round 6
// baseline (speedup 1.0000x reference)
#include <cuda_runtime.h>
#include <cuda_bf16.h>
#include <math.h>
#include <stdint.h>

static constexpr int B_ = 16;
static constexpr int S_ = 512;
static constexpr int C_ = 7;
static constexpr int D_ = 512;
static constexpr int H_ = 8;
static constexpr int E_ = 64;
static constexpr int DFF_ = 2048;
static constexpr int L_ = 3;
static constexpr int NCLS_ = 10;
static constexpr int PH_ = 64;

// ---------------- scratch ----------------
__device__ float g_x[B_*S_*D_];
__device__ float g_q[B_*S_*D_];
__device__ float g_k[B_*S_*D_];
__device__ float g_v[B_*S_*D_];
__device__ float g_o[B_*S_*D_];
__device__ float g_tmp[B_*S_*D_];
__device__ float g_ffn[B_*S_*DFF_];
__device__ float g_attn[B_*H_*S_*S_];
__device__ float g_tau[B_];
__device__ float g_delta[B_*S_];
__device__ float g_final[B_*S_*D_];

__device__ __forceinline__ float gelu_f(float x) {
    return 0.5f * x * (1.0f + erff(x * 0.70710678118654752440f));
}

__device__ __forceinline__ void mma16816(float* c, const uint32_t* a, const uint32_t* b) {
    asm volatile(
        "mma.sync.aligned.m16n8k16.row.col.f32.bf16.bf16.f32 "
        "{%0,%1,%2,%3}, {%4,%5,%6,%7}, {%8,%9}, {%0,%1,%2,%3};"
        : "+f"(c[0]), "+f"(c[1]), "+f"(c[2]), "+f"(c[3])
        : "r"(a[0]), "r"(a[1]), "r"(a[2]), "r"(a[3]), "r"(b[0]), "r"(b[1]));
}

// split one float pair (x = k even, y = k odd) into hi/lo bf16x2 (low half = x)
__device__ __forceinline__ void split2(float x, float y, uint32_t& hi, uint32_t& lo) {
    __nv_bfloat162 h = __floats2bfloat162_rn(x, y);
    float hx = __low2float(h), hy = __high2float(h);
    __nv_bfloat162 l = __floats2bfloat162_rn(x - hx, y - hy);
    hi = *(uint32_t*)&h;
    lo = *(uint32_t*)&l;
}

// ================= bf16-split 3-pass mma GEMM, double-buffered =================
// C[128 x NT] = A[128 x K] * B^T + epi.  batched via blockIdx.z (bb*hmod+hh).
// BT=false: B is [N][K] row-major (k contig). BT=true: B is [K][N] (n contig).
// EPI: 0 = +bias(if set); 1 = gelu(+bias); 2 = 0.125*(c*tau[bb] + delta[bb*S+n])
// dynamic smem stage layout (u32 units):
//   [0,2048)         A hi   [kt(2)][msub(8)][lane*4 regs]
//   [2048,4096)      A lo
//   [4096,4096+2*NSUB*64)          B hi  [kt(2)][nsub][lane*2 regs]
//   [...,+2*NSUB*64)               B lo
template<int EPI, int NT, bool BT>
__global__ void __launch_bounds__(256, 1) mma_gemm(
    const float* __restrict__ A, int lda, long dA, long mA,
    const float* __restrict__ Bs, int ldb, long dB, long mB,
    const float* __restrict__ bias,
    float* __restrict__ Cc, int ldc, long dC, long mC,
    int K, int hmod,
    const float* __restrict__ tau, const float* __restrict__ delta)
{
    constexpr int NSUB  = NT / 8;
    constexpr int NSUBW = NSUB / 2;
    constexpr int BSZ   = 2 * NSUB * 64;       // u32 per B matrix per stage
    constexpr int SSZ   = 4096 + 2 * BSZ;      // u32 per stage
    constexpr int NB    = NT / 32;             // B prefetch float4 count

    extern __shared__ uint32_t smem[];

    const int tid = threadIdx.x, wid = tid >> 5, lane = tid & 31;
    const int mw = wid & 3, nw = wid >> 2;
    const int bz = blockIdx.z;
    const int bb = bz / hmod, hh = bz - bb * hmod;
    A  += (long)bb * dA + (long)hh * mA;
    Bs += (long)bb * dB + (long)hh * mB;
    Cc += (long)bb * dC + (long)hh * mC;
    const int m0 = blockIdx.x * 128;
    const int n0 = blockIdx.y * NT;

    float acc[2][NSUBW][4];
    #pragma unroll
    for (int i = 0; i < 2; i++)
        #pragma unroll
        for (int j = 0; j < NSUBW; j++)
            #pragma unroll
            for (int r = 0; r < 4; r++) acc[i][j][r] = 0.f;

    float4 ra[4], rb[NB];

    auto ldgA = [&](int c) {
        const float* ap = A + c * 32;
        #pragma unroll
        for (int j = 0; j < 4; j++) {
            int idx = j * 256 + tid;
            int r = idx >> 3, f = idx & 7;
            ra[j] = *(const float4*)(ap + (long)(m0 + r) * lda + f * 4);
        }
    };
    auto ldgB = [&](int c) {
        if (!BT) {
            const float* bp = Bs + c * 32;
            #pragma unroll
            for (int j = 0; j < NB; j++) {
                int idx = j * 256 + tid;
                int r = idx >> 3, f = idx & 7;
                rb[j] = *(const float4*)(bp + (long)(n0 + r) * ldb + f * 4);
            }
        } else {
            #pragma unroll
            for (int j = 0; j < NB; j++) {
                int idx = j * 256 + tid;
                int kk = idx / (NT / 4);
                int n4 = (idx % (NT / 4)) * 4;
                rb[j] = *(const float4*)(Bs + (long)(c * 32 + kk) * ldb + n0 + n4);
            }
        }
    };
    auto stsStage = [&](int st) {
        uint32_t* dAhi = smem + st * SSZ;
        uint32_t* dAlo = dAhi + 2048;
        uint32_t* dBhi = dAhi + 4096;
        uint32_t* dBlo = dBhi + BSZ;
        #pragma unroll
        for (int j = 0; j < 4; j++) {
            int idx = j * 256 + tid;
            int r = idx >> 3, f = idx & 7, kl = f * 4;
            uint32_t h01, l01, h23, l23;
            split2(ra[j].x, ra[j].y, h01, l01);
            split2(ra[j].z, ra[j].w, h23, l23);
            int kt = kl >> 4, ck = kl & 15;
            int msub = r >> 4, r16 = r & 15;
            int reg = (r16 >> 3) + ((ck >> 3) << 1);
            int laneA = ((r16 & 7) << 2) + ((ck >> 1) & 3);
            int base = ((kt * 8 + msub) << 7) + reg;
            dAhi[base + laneA * 4]       = h01;
            dAhi[base + (laneA + 1) * 4] = h23;
            dAlo[base + laneA * 4]       = l01;
            dAlo[base + (laneA + 1) * 4] = l23;
        }
        if (!BT) {
            #pragma unroll
            for (int j = 0; j < NB; j++) {
                int idx = j * 256 + tid;
                int r = idx >> 3, f = idx & 7, kl = f * 4;
                uint32_t h01, l01, h23, l23;
                split2(rb[j].x, rb[j].y, h01, l01);
                split2(rb[j].z, rb[j].w, h23, l23);
                int kt = kl >> 4, ck = kl & 15;
                int nsub = r >> 3;
                int reg = ck >> 3;
                int laneB = ((r & 7) << 2) + ((ck & 7) >> 1);
                int base = ((kt * NSUB + nsub) << 6) + reg;
                dBhi[base + laneB * 2]       = h01;
                dBhi[base + (laneB + 1) * 2] = h23;
                dBlo[base + laneB * 2]       = l01;
                dBlo[base + (laneB + 1) * 2] = l23;
            }
        } else {
            uint16_t* bh16 = (uint16_t*)dBhi;
            uint16_t* bl16 = (uint16_t*)dBlo;
            #pragma unroll
            for (int j = 0; j < NB; j++) {
                int idx = j * 256 + tid;
                int kk = idx / (NT / 4);
                int n4 = (idx % (NT / 4)) * 4;
                float vv[4] = { rb[j].x, rb[j].y, rb[j].z, rb[j].w };
                int kt = kk >> 4, ck = kk & 15;
                int reg = ck >> 3, half = ck & 1;
                #pragma unroll
                for (int e = 0; e < 4; e++) {
                    int n = n4 + e;
                    __nv_bfloat16 hb = __float2bfloat16_rn(vv[e]);
                    uint16_t hu = *(uint16_t*)&hb;
                    float hf = __uint_as_float((uint32_t)hu << 16);
                    __nv_bfloat16 lb = __float2bfloat16_rn(vv[e] - hf);
                    int laneB = ((n & 7) << 2) + ((ck & 7) >> 1);
                    int u16i = (((kt * NSUB + (n >> 3)) << 6) + laneB * 2 + reg) * 2 + half;
                    bh16[u16i] = hu;
                    bl16[u16i] = *(uint16_t*)&lb;
                }
            }
        }
    };

    const int nchunk = K >> 5;

    // prologue: fill stage 0
    ldgA(0); ldgB(0);
    stsStage(0);
    __syncthreads();

    for (int c = 0; c < nchunk; c++) {
        const bool more = (c + 1 < nchunk);
        if (more) { ldgA(c + 1); ldgB(c + 1); }   // in-flight during compute

        const uint32_t* bAhi = smem + (c & 1) * SSZ;
        const uint32_t* bAlo = bAhi + 2048;
        const uint32_t* bBhi = bAhi + 4096;
        const uint32_t* bBlo = bBhi + BSZ;

        #pragma unroll
        for (int kt = 0; kt < 2; kt++) {
            uint32_t ah[2][4], al[2][4];
            #pragma unroll
            for (int ms = 0; ms < 2; ms++) {
                int msub = mw * 2 + ms;
                int ai = ((kt * 8 + msub) << 7) + lane * 4;
                *(uint4*)ah[ms] = *(const uint4*)&bAhi[ai];
                *(uint4*)al[ms] = *(const uint4*)&bAlo[ai];
            }
            #pragma unroll
            for (int ns = 0; ns < NSUBW; ns++) {
                int nsub = nw * NSUBW + ns;
                int bi = ((kt * NSUB + nsub) << 6) + lane * 2;
                uint32_t bh[2], bl[2];
                *(uint2*)bh = *(const uint2*)&bBhi[bi];
                *(uint2*)bl = *(const uint2*)&bBlo[bi];
                #pragma unroll
                for (int ms = 0; ms < 2; ms++) {
                    mma16816(acc[ms][ns], ah[ms], bh);
                    mma16816(acc[ms][ns], ah[ms], bl);
                    mma16816(acc[ms][ns], al[ms], bh);
                }
            }
        }

        if (more) {
            stsStage((c + 1) & 1);
            __syncthreads();
        }
    }

    // ---- epilogue ----
    const float tv = (EPI == 2) ? tau[bb] : 0.f;
    const float* dp = (EPI == 2) ? delta + (long)bb * S_ : nullptr;
    #pragma unroll
    for (int ms = 0; ms < 2; ms++) {
        #pragma unroll
        for (int ns = 0; ns < NSUBW; ns++) {
            int m = m0 + mw * 32 + ms * 16 + (lane >> 2);
            int n = n0 + nw * (NSUBW * 8) + ns * 8 + (lane & 3) * 2;
            float* cr = acc[ms][ns];
            float b0 = 0.f, b1 = 0.f;
            if (EPI != 2 && bias) { b0 = bias[n]; b1 = bias[n + 1]; }
            #pragma unroll
            for (int h = 0; h < 2; h++) {
                float c0 = cr[h * 2 + 0], c1 = cr[h * 2 + 1];
                if (EPI == 2) {
                    c0 = 0.125f * (c0 * tv + dp[n]);
                    c1 = 0.125f * (c1 * tv + dp[n + 1]);
                } else {
                    c0 += b0; c1 += b1;
                    if (EPI == 1) { c0 = gelu_f(c0); c1 = gelu_f(c1); }
                }
                float2 o; o.x = c0; o.y = c1;
                *(float2*)(Cc + (long)(m + h * 8) * ldc + n) = o;
            }
        }
    }
}

// ---------------- tau/delta projectors ----------------
__global__ void proj_kernel(const float* __restrict__ x_enc,
                            const float* __restrict__ tau_conv, const float* __restrict__ tau_w1,
                            const float* __restrict__ tau_b1, const float* __restrict__ tau_w2,
                            const float* __restrict__ del_conv, const float* __restrict__ del_w1,
                            const float* __restrict__ del_b1, const float* __restrict__ del_w2)
{
    int b = blockIdx.x;
    int tid = threadIdx.x;               // 256
    __shared__ float s_mean[C_], s_std[C_], s_yt[C_], s_yd[C_], s_ht[PH_], s_hd[PH_];

    if (tid < C_) {
        float s = 0.f, s2 = 0.f;
        for (int i = 0; i < S_; i++) {
            float v = x_enc[((long)b*S_ + i)*C_ + tid];
            s += v; s2 += v*v;
        }
        float mu = s * (1.f/S_);
        s_mean[tid] = mu;
        s_std[tid] = sqrtf(fmaxf(s2*(1.f/S_) - mu*mu, 0.f) + 1e-5f);
    }
    int w = tid >> 5, lane = tid & 31;
    if (w < C_) {
        int j = w;
        int jm = (j+6)%7, jp = (j+1)%7;
        float at = 0.f, ad = 0.f;
        for (int i = lane; i < S_; i += 32) {
            const float* xr = x_enc + ((long)b*S_ + i)*C_;
            float x0 = xr[jm], x1 = xr[j], x2 = xr[jp];
            const float* wt = tau_conv + i*3;
            const float* wd = del_conv + i*3;
            at += wt[0]*x0 + wt[1]*x1 + wt[2]*x2;
            ad += wd[0]*x0 + wd[1]*x1 + wd[2]*x2;
        }
        #pragma unroll
        for (int o = 16; o; o >>= 1) {
            at += __shfl_xor_sync(0xffffffffu, at, o);
            ad += __shfl_xor_sync(0xffffffffu, ad, o);
        }
        if (lane == 0) { s_yt[j] = at; s_yd[j] = ad; }
    }
    __syncthreads();
    if (tid < PH_) {
        float st = tau_b1[tid], sd = del_b1[tid];
        #pragma unroll
        for (int f = 0; f < 14; f++) {
            float ft = (f < 7) ? s_yt[f] : s_std[f-7];
            float fd = (f < 7) ? s_yd[f] : s_mean[f-7];
            st += tau_w1[tid*14 + f] * ft;
            sd += del_w1[tid*14 + f] * fd;
        }
        s_ht[tid] = fmaxf(st, 0.f);
        s_hd[tid] = fmaxf(sd, 0.f);
    }
    __syncthreads();
    if (tid < 32) {
        float t = s_ht[tid]*tau_w2[tid] + s_ht[tid+32]*tau_w2[tid+32];
        #pragma unroll
        for (int o = 16; o; o >>= 1) t += __shfl_xor_sync(0xffffffffu, t, o);
        if (tid == 0) g_tau[b] = expf(t);
    }
    for (int s = tid; s < S_; s += 256) {
        float acc = 0.f;
        const float* wr = del_w2 + s*PH_;
        #pragma unroll
        for (int p = 0; p < PH_; p++) acc += s_hd[p] * wr[p];
        g_delta[(long)b*S_ + s] = acc;
    }
}

// ---------------- token embedding + positional encoding ----------------
__global__ void embed_kernel(const float* __restrict__ x_enc, const float* __restrict__ tok_w)
{
    int row = blockIdx.x;                // b*S + s
    int b = row / S_, s = row % S_;
    __shared__ float xs[3][C_];
    int tid = threadIdx.x;               // 128
    if (tid < 21) {
        int r = tid / 7, c = tid % 7;
        int sp = (s - 1 + r + S_) % S_;
        xs[r][c] = x_enc[((long)b*S_ + sp)*C_ + c];
    }
    __syncthreads();
    for (int d = tid; d < D_; d += 128) {
        int dd = d & ~1;
        float div = expf((float)dd * (-9.2103403719761836f / (float)D_));
        float ang = (float)s * div;
        float pe = (d & 1) ? cosf(ang) : sinf(ang);
        float acc = pe;
        const float* wp = tok_w + d*21;
        #pragma unroll
        for (int r = 0; r < 3; r++)
            #pragma unroll
            for (int c = 0; c < 7; c++)
                acc = fmaf(wp[c*3 + r], xs[r][c], acc);
        g_x[(long)row*D_ + d] = acc;
    }
}

// ---------------- softmax over rows of 512 ----------------
__global__ void softmax_kernel(float* __restrict__ A)
{
    long row = blockIdx.x;
    float* p = A + row * S_;
    int tid = threadIdx.x;               // 128
    float v[4];
    #pragma unroll
    for (int i = 0; i < 4; i++) v[i] = p[tid + i*128];
    float m = fmaxf(fmaxf(v[0], v[1]), fmaxf(v[2], v[3]));
    __shared__ float sh[4];
    #pragma unroll
    for (int o = 16; o; o >>= 1) m = fmaxf(m, __shfl_xor_sync(0xffffffffu, m, o));
    int w = tid >> 5, lane = tid & 31;
    if (lane == 0) sh[w] = m;
    __syncthreads();
    m = fmaxf(fmaxf(sh[0], sh[1]), fmaxf(sh[2], sh[3]));
    __syncthreads();
    float s = 0.f;
    #pragma unroll
    for (int i = 0; i < 4; i++) { v[i] = expf(v[i] - m); s += v[i]; }
    #pragma unroll
    for (int o = 16; o; o >>= 1) s += __shfl_xor_sync(0xffffffffu, s, o);
    if (lane == 0) sh[w] = s;
    __syncthreads();
    s = sh[0] + sh[1] + sh[2] + sh[3];
    float inv = 1.f / s;
    #pragma unroll
    for (int i = 0; i < 4; i++) p[tid + i*128] = v[i] * inv;
}

// ---------------- residual add + LayerNorm ----------------
__global__ void add_ln_kernel(const float* __restrict__ xr, const float* __restrict__ ar,
                              const float* __restrict__ g, const float* __restrict__ bt,
                              float* __restrict__ out)
{
    long row = blockIdx.x;
    int tid = threadIdx.x;               // 128
    const float* xp = xr + row*D_;
    const float* ap = ar + row*D_;
    float v[4];
    float s = 0.f, s2 = 0.f;
    #pragma unroll
    for (int i = 0; i < 4; i++) {
        float t = xp[tid + i*128] + ap[tid + i*128];
        v[i] = t; s += t; s2 += t*t;
    }
    __shared__ float shs[4], sh2[4];
    #pragma unroll
    for (int o = 16; o; o >>= 1) {
        s  += __shfl_xor_sync(0xffffffffu, s, o);
        s2 += __shfl_xor_sync(0xffffffffu, s2, o);
    }
    int w = tid >> 5, lane = tid & 31;
    if (lane == 0) { shs[w] = s; sh2[w] = s2; }
    __syncthreads();
    s  = shs[0] + shs[1] + shs[2] + shs[3];
    s2 = sh2[0] + sh2[1] + sh2[2] + sh2[3];
    float mean = s * (1.f/D_);
    float var = s2 * (1.f/D_) - mean*mean;
    float r = rsqrtf(var + 1e-5f);
    #pragma unroll
    for (int i = 0; i < 4; i++) {
        int c = tid + i*128;
        out[row*D_ + c] = (v[i] - mean) * r * g[c] + bt[c];
    }
}

// ---------------- final LN + GELU + mask ----------------
__global__ void lnf_kernel(const float* __restrict__ xr,
                           const float* __restrict__ g, const float* __restrict__ bt,
                           const float* __restrict__ mark, float* __restrict__ out)
{
    long row = blockIdx.x;
    int tid = threadIdx.x;               // 128
    const float* xp = xr + row*D_;
    float v[4];
    float s = 0.f, s2 = 0.f;
    #pragma unroll
    for (int i = 0; i < 4; i++) {
        float t = xp[tid + i*128];
        v[i] = t; s += t; s2 += t*t;
    }
    __shared__ float shs[4], sh2[4];
    #pragma unroll
    for (int o = 16; o; o >>= 1) {
        s  += __shfl_xor_sync(0xffffffffu, s, o);
        s2 += __shfl_xor_sync(0xffffffffu, s2, o);
    }
    int w = tid >> 5, lane = tid & 31;
    if (lane == 0) { shs[w] = s; sh2[w] = s2; }
    __syncthreads();
    s  = shs[0] + shs[1] + shs[2] + shs[3];
    s2 = sh2[0] + sh2[1] + sh2[2] + sh2[3];
    float mean = s * (1.f/D_);
    float var = s2 * (1.f/D_) - mean*mean;
    float r = rsqrtf(var + 1e-5f);
    float mk = mark[row];
    #pragma unroll
    for (int i = 0; i < 4; i++) {
        int c = tid + i*128;
        float val = (v[i] - mean) * r * g[c] + bt[c];
        out[row*D_ + c] = gelu_f(val) * mk;
    }
}

// ---------------- final classifier GEMV ----------------
__global__ void final_kernel(const float* __restrict__ gfin, const float* __restrict__ pw,
                             const float* __restrict__ pb, float* __restrict__ out)
{
    int idx = blockIdx.x;
    int b = idx / NCLS_, n = idx - b*NCLS_;
    const float* gp = gfin + (long)b*S_*D_;
    const float* wp = pw + (long)n*S_*D_;
    float s = 0.f;
    for (int k = threadIdx.x*4; k < S_*D_; k += 256*4) {
        float4 a  = *(const float4*)(gp + k);
        float4 w4 = *(const float4*)(wp + k);
        s += a.x*w4.x + a.y*w4.y + a.z*w4.z + a.w*w4.w;
    }
    __shared__ float sh[8];
    #pragma unroll
    for (int o = 16; o; o >>= 1) s += __shfl_xor_sync(0xffffffffu, s, o);
    if ((threadIdx.x & 31) == 0) sh[threadIdx.x >> 5] = s;
    __syncthreads();
    if (threadIdx.x == 0) {
        float t = 0.f;
        #pragma unroll
        for (int i = 0; i < 8; i++) t += sh[i];
        out[idx] = t + pb[n];
    }
}

// ---------------- host ----------------
extern "C" void kernel_launch(void* const* d_in, const int* in_sizes, int n_in,
                              void* d_out, int out_size)
{
    const float* x_enc    = (const float*)d_in[0];
    const float* x_mark   = (const float*)d_in[1];
    const float* tok_w    = (const float*)d_in[2];
    const float* Wq       = (const float*)d_in[3];
    const float* bq       = (const float*)d_in[4];
    const float* Wk       = (const float*)d_in[5];
    const float* bk       = (const float*)d_in[6];
    const float* Wv       = (const float*)d_in[7];
    const float* bv       = (const float*)d_in[8];
    const float* Wo       = (const float*)d_in[9];
    const float* bo       = (const float*)d_in[10];
    const float* W1       = (const float*)d_in[11];
    const float* b1       = (const float*)d_in[12];
    const float* W2       = (const float*)d_in[13];
    const float* b2       = (const float*)d_in[14];
    const float* ln1g     = (const float*)d_in[15];
    const float* ln1b     = (const float*)d_in[16];
    const float* ln2g     = (const float*)d_in[17];
    const float* ln2b     = (const float*)d_in[18];
    const float* lnfg     = (const float*)d_in[19];
    const float* lnfb     = (const float*)d_in[20];
    const float* proj_w   = (const float*)d_in[21];
    const float* proj_b   = (const float*)d_in[22];
    const float* tau_conv = (const float*)d_in[23];
    const float* tau_w1   = (const float*)d_in[24];
    const float* tau_b1   = (const float*)d_in[25];
    const float* tau_w2   = (const float*)d_in[26];
    const float* del_conv = (const float*)d_in[27];
    const float* del_w1   = (const float*)d_in[28];
    const float* del_b1   = (const float*)d_in[29];
    const float* del_w2   = (const float*)d_in[30];

    float *px, *pq, *pk, *pv, *po, *ptmp, *pffn, *pattn, *ptau, *pdelta, *pfin;
    cudaGetSymbolAddress((void**)&px,    g_x);
    cudaGetSymbolAddress((void**)&pq,    g_q);
    cudaGetSymbolAddress((void**)&pk,    g_k);
    cudaGetSymbolAddress((void**)&pv,    g_v);
    cudaGetSymbolAddress((void**)&po,    g_o);
    cudaGetSymbolAddress((void**)&ptmp,  g_tmp);
    cudaGetSymbolAddress((void**)&pffn,  g_ffn);
    cudaGetSymbolAddress((void**)&pattn, g_attn);
    cudaGetSymbolAddress((void**)&ptau,  g_tau);
    cudaGetSymbolAddress((void**)&pdelta,g_delta);
    cudaGetSymbolAddress((void**)&pfin,  g_final);

    // dynamic smem: 2 stages
    const int SM128 = 2 * (4096 + 2*2*16*64) * 4;   // 65536 bytes (NT=128)
    const int SM64  = 2 * (4096 + 2*2*8*64) * 4;    // 49152 bytes (NT=64)
    cudaFuncSetAttribute(mma_gemm<0,128,false>, cudaFuncAttributeMaxDynamicSharedMemorySize, SM128);
    cudaFuncSetAttribute(mma_gemm<1,128,false>, cudaFuncAttributeMaxDynamicSharedMemorySize, SM128);
    cudaFuncSetAttribute(mma_gemm<2,128,false>, cudaFuncAttributeMaxDynamicSharedMemorySize, SM128);
    cudaFuncSetAttribute(mma_gemm<0,64,true>,   cudaFuncAttributeMaxDynamicSharedMemorySize, SM64);

    proj_kernel<<<B_, 256>>>(x_enc, tau_conv, tau_w1, tau_b1, tau_w2,
                             del_conv, del_w1, del_b1, del_w2);
    embed_kernel<<<B_*S_, 128>>>(x_enc, tok_w);

    const int M = B_*S_;                          // 8192
    dim3 gQKV(M/128, D_/128, 1);                  // (64, 4)
    dim3 gFF1(M/128, DFF_/128, 1);                // (64, 16)
    dim3 gQK(S_/128, S_/128, B_*H_);              // (4, 4, 128)
    dim3 gAV(S_/128, 1, B_*H_);                   // (4, 1, 128)
    const long sBD = (long)S_*D_;
    const long sHSS = (long)H_*S_*S_;
    const long sSS = (long)S_*S_;

    for (int l = 0; l < L_; l++) {
        const float* wq = Wq + (long)l*D_*D_;
        const float* wk = Wk + (long)l*D_*D_;
        const float* wv = Wv + (long)l*D_*D_;
        const float* wo = Wo + (long)l*D_*D_;

        mma_gemm<0,128,false><<<gQKV, 256, SM128>>>(px, D_, 0, 0, wq, D_, 0, 0, bq + l*D_,
                                                    pq, D_, 0, 0, D_, 1, nullptr, nullptr);
        mma_gemm<0,128,false><<<gQKV, 256, SM128>>>(px, D_, 0, 0, wk, D_, 0, 0, bk + l*D_,
                                                    pk, D_, 0, 0, D_, 1, nullptr, nullptr);
        mma_gemm<0,128,false><<<gQKV, 256, SM128>>>(px, D_, 0, 0, wv, D_, 0, 0, bv + l*D_,
                                                    pv, D_, 0, 0, D_, 1, nullptr, nullptr);

        // logits[b,h,l,s] = 0.125 * (q.k * tau[b] + delta[b,s])
        mma_gemm<2,128,false><<<gQK, 256, SM128>>>(pq, D_, sBD, E_, pk, D_, sBD, E_, nullptr,
                                                   pattn, S_, sHSS, sSS, E_, H_, ptau, pdelta);
        softmax_kernel<<<B_*H_*S_, 128>>>(pattn);
        // o = A @ V   (B operand = V accessed transposed)
        mma_gemm<0,64,true><<<gAV, 256, SM64>>>(pattn, S_, sHSS, sSS, pv, D_, sBD, E_, nullptr,
                                                po, D_, sBD, E_, S_, H_, nullptr, nullptr);

        mma_gemm<0,128,false><<<gQKV, 256, SM128>>>(po, D_, 0, 0, wo, D_, 0, 0, bo + l*D_,
                                                    ptmp, D_, 0, 0, D_, 1, nullptr, nullptr);
        add_ln_kernel<<<B_*S_, 128>>>(px, ptmp, ln1g + l*D_, ln1b + l*D_, px);

        mma_gemm<1,128,false><<<gFF1, 256, SM128>>>(px, D_, 0, 0, W1 + (long)l*DFF_*D_, D_, 0, 0,
                                                    b1 + l*DFF_, pffn, DFF_, 0, 0, D_, 1, nullptr, nullptr);
        mma_gemm<0,128,false><<<gQKV, 256, SM128>>>(pffn, DFF_, 0, 0, W2 + (long)l*D_*DFF_, DFF_, 0, 0,
                                                    b2 + l*D_, ptmp, D_, 0, 0, DFF_, 1, nullptr, nullptr);
        add_ln_kernel<<<B_*S_, 128>>>(px, ptmp, ln2g + l*D_, ln2b + l*D_, px);
    }

    lnf_kernel<<<B_*S_, 128>>>(px, lnfg, lnfb, x_mark, pfin);
    final_kernel<<<B_*NCLS_, 256>>>(pfin, proj_w, proj_b, (float*)d_out);
}

// round 7
// speedup vs baseline: 1.6435x; 1.6435x over previous
#include <cuda_runtime.h>
#include <cuda_fp16.h>
#include <math.h>
#include <stdint.h>

static constexpr int B_ = 16;
static constexpr int S_ = 512;
static constexpr int C_ = 7;
static constexpr int D_ = 512;
static constexpr int H_ = 8;
static constexpr int E_ = 64;
static constexpr int DFF_ = 2048;
static constexpr int L_ = 3;
static constexpr int NCLS_ = 10;
static constexpr int PH_ = 64;

// ---------------- scratch ----------------
__device__ float g_x[B_*S_*D_];
__device__ float g_q[B_*S_*D_];
__device__ float g_k[B_*S_*D_];
__device__ float g_v[B_*S_*D_];
__device__ float g_o[B_*S_*D_];
__device__ float g_tmp[B_*S_*D_];
__device__ float g_ffn[B_*S_*DFF_];
__device__ float g_attn[B_*H_*S_*S_];
__device__ float g_tau[B_];
__device__ float g_delta[B_*S_];
__device__ float g_final[B_*S_*D_];

__device__ __forceinline__ float gelu_f(float x) {
    return 0.5f * x * (1.0f + erff(x * 0.70710678118654752440f));
}

__device__ __forceinline__ void mma16816(float* c, const uint32_t* a, const uint32_t* b) {
    asm volatile(
        "mma.sync.aligned.m16n8k16.row.col.f32.f16.f16.f32 "
        "{%0,%1,%2,%3}, {%4,%5,%6,%7}, {%8,%9}, {%0,%1,%2,%3};"
        : "+f"(c[0]), "+f"(c[1]), "+f"(c[2]), "+f"(c[3])
        : "r"(a[0]), "r"(a[1]), "r"(a[2]), "r"(a[3]), "r"(b[0]), "r"(b[1]));
}

// pack float pair (x = k even, y = k odd) into one fp16x2 register
__device__ __forceinline__ uint32_t cvt2(float x, float y) {
    __half2 h = __floats2half2_rn(x, y);
    return *(uint32_t*)&h;
}

// ================= fp16 single-pass mma GEMM, double-buffered =================
// C[128 x NT] = A[128 x K] * B^T + epi.  batched via blockIdx.z (bb*hmod+hh).
// BT=false: B is [N][K] row-major (k contig). BT=true: B is [K][N] (n contig).
// EPI: 0 = +bias(if set); 1 = gelu(+bias); 2 = 0.125*(c*tau[bb] + delta[bb*S+n])
// dynamic smem stage layout (u32 units):
//   [0,2048)            A    [kt(2)][msub(8)][lane(32)*4 regs]
//   [2048,2048+BSZ)     B    [kt(2)][nsub(NSUB)][lane(32)*2 regs]
template<int EPI, int NT, bool BT>
__global__ void __launch_bounds__(256, 2) mma_gemm(
    const float* __restrict__ A, int lda, long dA, long mA,
    const float* __restrict__ Bs, int ldb, long dB, long mB,
    const float* __restrict__ bias,
    float* __restrict__ Cc, int ldc, long dC, long mC,
    int K, int hmod,
    const float* __restrict__ tau, const float* __restrict__ delta)
{
    constexpr int NSUB  = NT / 8;
    constexpr int NSUBW = NSUB / 2;
    constexpr int BSZ   = 2 * NSUB * 64;       // u32 for B per stage
    constexpr int SSZ   = 2048 + BSZ;          // u32 per stage
    constexpr int NB    = NT / 32;             // B prefetch float4 count

    extern __shared__ uint32_t smem[];

    const int tid = threadIdx.x, wid = tid >> 5, lane = tid & 31;
    const int mw = wid & 3, nw = wid >> 2;
    const int bz = blockIdx.z;
    const int bb = bz / hmod, hh = bz - bb * hmod;
    A  += (long)bb * dA + (long)hh * mA;
    Bs += (long)bb * dB + (long)hh * mB;
    Cc += (long)bb * dC + (long)hh * mC;
    const int m0 = blockIdx.x * 128;
    const int n0 = blockIdx.y * NT;

    float acc[2][NSUBW][4];
    #pragma unroll
    for (int i = 0; i < 2; i++)
        #pragma unroll
        for (int j = 0; j < NSUBW; j++)
            #pragma unroll
            for (int r = 0; r < 4; r++) acc[i][j][r] = 0.f;

    float4 ra[4], rb[NB];

    auto ldgA = [&](int c) {
        const float* ap = A + c * 32;
        #pragma unroll
        for (int j = 0; j < 4; j++) {
            int idx = j * 256 + tid;
            int r = idx >> 3, f = idx & 7;
            ra[j] = *(const float4*)(ap + (long)(m0 + r) * lda + f * 4);
        }
    };
    auto ldgB = [&](int c) {
        if (!BT) {
            const float* bp = Bs + c * 32;
            #pragma unroll
            for (int j = 0; j < NB; j++) {
                int idx = j * 256 + tid;
                int r = idx >> 3, f = idx & 7;
                rb[j] = *(const float4*)(bp + (long)(n0 + r) * ldb + f * 4);
            }
        } else {
            #pragma unroll
            for (int j = 0; j < NB; j++) {
                int idx = j * 256 + tid;
                int kk = idx / (NT / 4);
                int n4 = (idx % (NT / 4)) * 4;
                rb[j] = *(const float4*)(Bs + (long)(c * 32 + kk) * ldb + n0 + n4);
            }
        }
    };
    auto stsStage = [&](int st) {
        uint32_t* dAp = smem + st * SSZ;
        uint32_t* dBp = dAp + 2048;
        #pragma unroll
        for (int j = 0; j < 4; j++) {
            int idx = j * 256 + tid;
            int r = idx >> 3, f = idx & 7, kl = f * 4;
            uint32_t h01 = cvt2(ra[j].x, ra[j].y);
            uint32_t h23 = cvt2(ra[j].z, ra[j].w);
            int kt = kl >> 4, ck = kl & 15;
            int msub = r >> 4, r16 = r & 15;
            int reg = (r16 >> 3) + ((ck >> 3) << 1);
            int laneA = ((r16 & 7) << 2) + ((ck >> 1) & 3);
            int base = ((kt * 8 + msub) << 7) + reg;
            dAp[base + laneA * 4]       = h01;
            dAp[base + (laneA + 1) * 4] = h23;
        }
        if (!BT) {
            #pragma unroll
            for (int j = 0; j < NB; j++) {
                int idx = j * 256 + tid;
                int r = idx >> 3, f = idx & 7, kl = f * 4;
                uint32_t h01 = cvt2(rb[j].x, rb[j].y);
                uint32_t h23 = cvt2(rb[j].z, rb[j].w);
                int kt = kl >> 4, ck = kl & 15;
                int nsub = r >> 3;
                int reg = ck >> 3;
                int laneB = ((r & 7) << 2) + ((ck & 7) >> 1);
                int base = ((kt * NSUB + nsub) << 6) + reg;
                dBp[base + laneB * 2]       = h01;
                dBp[base + (laneB + 1) * 2] = h23;
            }
        } else {
            uint16_t* bh16 = (uint16_t*)dBp;
            #pragma unroll
            for (int j = 0; j < NB; j++) {
                int idx = j * 256 + tid;
                int kk = idx / (NT / 4);
                int n4 = (idx % (NT / 4)) * 4;
                float vv[4] = { rb[j].x, rb[j].y, rb[j].z, rb[j].w };
                int kt = kk >> 4, ck = kk & 15;
                int reg = ck >> 3, half = ck & 1;
                #pragma unroll
                for (int e = 0; e < 4; e++) {
                    int n = n4 + e;
                    __half hb = __float2half_rn(vv[e]);
                    int laneB = ((n & 7) << 2) + ((ck & 7) >> 1);
                    int u16i = (((kt * NSUB + (n >> 3)) << 6) + laneB * 2 + reg) * 2 + half;
                    bh16[u16i] = *(uint16_t*)&hb;
                }
            }
        }
    };

    const int nchunk = K >> 5;

    // prologue: fill stage 0
    ldgA(0); ldgB(0);
    stsStage(0);
    __syncthreads();

    for (int c = 0; c < nchunk; c++) {
        const bool more = (c + 1 < nchunk);
        if (more) { ldgA(c + 1); ldgB(c + 1); }   // in flight during compute

        const uint32_t* bAp = smem + (c & 1) * SSZ;
        const uint32_t* bBp = bAp + 2048;

        #pragma unroll
        for (int kt = 0; kt < 2; kt++) {
            uint32_t ah[2][4];
            #pragma unroll
            for (int ms = 0; ms < 2; ms++) {
                int msub = mw * 2 + ms;
                int ai = ((kt * 8 + msub) << 7) + lane * 4;
                *(uint4*)ah[ms] = *(const uint4*)&bAp[ai];
            }
            #pragma unroll
            for (int ns = 0; ns < NSUBW; ns++) {
                int nsub = nw * NSUBW + ns;
                int bi = ((kt * NSUB + nsub) << 6) + lane * 2;
                uint32_t bh[2];
                *(uint2*)bh = *(const uint2*)&bBp[bi];
                #pragma unroll
                for (int ms = 0; ms < 2; ms++)
                    mma16816(acc[ms][ns], ah[ms], bh);
            }
        }

        if (more) {
            stsStage((c + 1) & 1);
            __syncthreads();
        }
    }

    // ---- epilogue ----
    const float tv = (EPI == 2) ? tau[bb] : 0.f;
    const float* dp = (EPI == 2) ? delta + (long)bb * S_ : nullptr;
    #pragma unroll
    for (int ms = 0; ms < 2; ms++) {
        #pragma unroll
        for (int ns = 0; ns < NSUBW; ns++) {
            int m = m0 + mw * 32 + ms * 16 + (lane >> 2);
            int n = n0 + nw * (NSUBW * 8) + ns * 8 + (lane & 3) * 2;
            float* cr = acc[ms][ns];
            float b0 = 0.f, b1 = 0.f;
            if (EPI != 2 && bias) { b0 = bias[n]; b1 = bias[n + 1]; }
            #pragma unroll
            for (int h = 0; h < 2; h++) {
                float c0 = cr[h * 2 + 0], c1 = cr[h * 2 + 1];
                if (EPI == 2) {
                    c0 = 0.125f * (c0 * tv + dp[n]);
                    c1 = 0.125f * (c1 * tv + dp[n + 1]);
                } else {
                    c0 += b0; c1 += b1;
                    if (EPI == 1) { c0 = gelu_f(c0); c1 = gelu_f(c1); }
                }
                float2 o; o.x = c0; o.y = c1;
                *(float2*)(Cc + (long)(m + h * 8) * ldc + n) = o;
            }
        }
    }
}

// ---------------- tau/delta projectors ----------------
__global__ void proj_kernel(const float* __restrict__ x_enc,
                            const float* __restrict__ tau_conv, const float* __restrict__ tau_w1,
                            const float* __restrict__ tau_b1, const float* __restrict__ tau_w2,
                            const float* __restrict__ del_conv, const float* __restrict__ del_w1,
                            const float* __restrict__ del_b1, const float* __restrict__ del_w2)
{
    int b = blockIdx.x;
    int tid = threadIdx.x;               // 256
    __shared__ float s_mean[C_], s_std[C_], s_yt[C_], s_yd[C_], s_ht[PH_], s_hd[PH_];

    if (tid < C_) {
        float s = 0.f, s2 = 0.f;
        for (int i = 0; i < S_; i++) {
            float v = x_enc[((long)b*S_ + i)*C_ + tid];
            s += v; s2 += v*v;
        }
        float mu = s * (1.f/S_);
        s_mean[tid] = mu;
        s_std[tid] = sqrtf(fmaxf(s2*(1.f/S_) - mu*mu, 0.f) + 1e-5f);
    }
    int w = tid >> 5, lane = tid & 31;
    if (w < C_) {
        int j = w;
        int jm = (j+6)%7, jp = (j+1)%7;
        float at = 0.f, ad = 0.f;
        for (int i = lane; i < S_; i += 32) {
            const float* xr = x_enc + ((long)b*S_ + i)*C_;
            float x0 = xr[jm], x1 = xr[j], x2 = xr[jp];
            const float* wt = tau_conv + i*3;
            const float* wd = del_conv + i*3;
            at += wt[0]*x0 + wt[1]*x1 + wt[2]*x2;
            ad += wd[0]*x0 + wd[1]*x1 + wd[2]*x2;
        }
        #pragma unroll
        for (int o = 16; o; o >>= 1) {
            at += __shfl_xor_sync(0xffffffffu, at, o);
            ad += __shfl_xor_sync(0xffffffffu, ad, o);
        }
        if (lane == 0) { s_yt[j] = at; s_yd[j] = ad; }
    }
    __syncthreads();
    if (tid < PH_) {
        float st = tau_b1[tid], sd = del_b1[tid];
        #pragma unroll
        for (int f = 0; f < 14; f++) {
            float ft = (f < 7) ? s_yt[f] : s_std[f-7];
            float fd = (f < 7) ? s_yd[f] : s_mean[f-7];
            st += tau_w1[tid*14 + f] * ft;
            sd += del_w1[tid*14 + f] * fd;
        }
        s_ht[tid] = fmaxf(st, 0.f);
        s_hd[tid] = fmaxf(sd, 0.f);
    }
    __syncthreads();
    if (tid < 32) {
        float t = s_ht[tid]*tau_w2[tid] + s_ht[tid+32]*tau_w2[tid+32];
        #pragma unroll
        for (int o = 16; o; o >>= 1) t += __shfl_xor_sync(0xffffffffu, t, o);
        if (tid == 0) g_tau[b] = expf(t);
    }
    for (int s = tid; s < S_; s += 256) {
        float acc = 0.f;
        const float* wr = del_w2 + s*PH_;
        #pragma unroll
        for (int p = 0; p < PH_; p++) acc += s_hd[p] * wr[p];
        g_delta[(long)b*S_ + s] = acc;
    }
}

// ---------------- token embedding + positional encoding ----------------
__global__ void embed_kernel(const float* __restrict__ x_enc, const float* __restrict__ tok_w)
{
    int row = blockIdx.x;                // b*S + s
    int b = row / S_, s = row % S_;
    __shared__ float xs[3][C_];
    int tid = threadIdx.x;               // 128
    if (tid < 21) {
        int r = tid / 7, c = tid % 7;
        int sp = (s - 1 + r + S_) % S_;
        xs[r][c] = x_enc[((long)b*S_ + sp)*C_ + c];
    }
    __syncthreads();
    for (int d = tid; d < D_; d += 128) {
        int dd = d & ~1;
        float div = expf((float)dd * (-9.2103403719761836f / (float)D_));
        float ang = (float)s * div;
        float pe = (d & 1) ? cosf(ang) : sinf(ang);
        float acc = pe;
        const float* wp = tok_w + d*21;
        #pragma unroll
        for (int r = 0; r < 3; r++)
            #pragma unroll
            for (int c = 0; c < 7; c++)
                acc = fmaf(wp[c*3 + r], xs[r][c], acc);
        g_x[(long)row*D_ + d] = acc;
    }
}

// ---------------- softmax over rows of 512 ----------------
__global__ void softmax_kernel(float* __restrict__ A)
{
    long row = blockIdx.x;
    float* p = A + row * S_;
    int tid = threadIdx.x;               // 128
    float v[4];
    #pragma unroll
    for (int i = 0; i < 4; i++) v[i] = p[tid + i*128];
    float m = fmaxf(fmaxf(v[0], v[1]), fmaxf(v[2], v[3]));
    __shared__ float sh[4];
    #pragma unroll
    for (int o = 16; o; o >>= 1) m = fmaxf(m, __shfl_xor_sync(0xffffffffu, m, o));
    int w = tid >> 5, lane = tid & 31;
    if (lane == 0) sh[w] = m;
    __syncthreads();
    m = fmaxf(fmaxf(sh[0], sh[1]), fmaxf(sh[2], sh[3]));
    __syncthreads();
    float s = 0.f;
    #pragma unroll
    for (int i = 0; i < 4; i++) { v[i] = expf(v[i] - m); s += v[i]; }
    #pragma unroll
    for (int o = 16; o; o >>= 1) s += __shfl_xor_sync(0xffffffffu, s, o);
    if (lane == 0) sh[w] = s;
    __syncthreads();
    s = sh[0] + sh[1] + sh[2] + sh[3];
    float inv = 1.f / s;
    #pragma unroll
    for (int i = 0; i < 4; i++) p[tid + i*128] = v[i] * inv;
}

// ---------------- residual add + LayerNorm ----------------
__global__ void add_ln_kernel(const float* __restrict__ xr, const float* __restrict__ ar,
                              const float* __restrict__ g, const float* __restrict__ bt,
                              float* __restrict__ out)
{
    long row = blockIdx.x;
    int tid = threadIdx.x;               // 128
    const float* xp = xr + row*D_;
    const float* ap = ar + row*D_;
    float v[4];
    float s = 0.f, s2 = 0.f;
    #pragma unroll
    for (int i = 0; i < 4; i++) {
        float t = xp[tid + i*128] + ap[tid + i*128];
        v[i] = t; s += t; s2 += t*t;
    }
    __shared__ float shs[4], sh2[4];
    #pragma unroll
    for (int o = 16; o; o >>= 1) {
        s  += __shfl_xor_sync(0xffffffffu, s, o);
        s2 += __shfl_xor_sync(0xffffffffu, s2, o);
    }
    int w = tid >> 5, lane = tid & 31;
    if (lane == 0) { shs[w] = s; sh2[w] = s2; }
    __syncthreads();
    s  = shs[0] + shs[1] + shs[2] + shs[3];
    s2 = sh2[0] + sh2[1] + sh2[2] + sh2[3];
    float mean = s * (1.f/D_);
    float var = s2 * (1.f/D_) - mean*mean;
    float r = rsqrtf(var + 1e-5f);
    #pragma unroll
    for (int i = 0; i < 4; i++) {
        int c = tid + i*128;
        out[row*D_ + c] = (v[i] - mean) * r * g[c] + bt[c];
    }
}

// ---------------- final LN + GELU + mask ----------------
__global__ void lnf_kernel(const float* __restrict__ xr,
                           const float* __restrict__ g, const float* __restrict__ bt,
                           const float* __restrict__ mark, float* __restrict__ out)
{
    long row = blockIdx.x;
    int tid = threadIdx.x;               // 128
    const float* xp = xr + row*D_;
    float v[4];
    float s = 0.f, s2 = 0.f;
    #pragma unroll
    for (int i = 0; i < 4; i++) {
        float t = xp[tid + i*128];
        v[i] = t; s += t; s2 += t*t;
    }
    __shared__ float shs[4], sh2[4];
    #pragma unroll
    for (int o = 16; o; o >>= 1) {
        s  += __shfl_xor_sync(0xffffffffu, s, o);
        s2 += __shfl_xor_sync(0xffffffffu, s2, o);
    }
    int w = tid >> 5, lane = tid & 31;
    if (lane == 0) { shs[w] = s; sh2[w] = s2; }
    __syncthreads();
    s  = shs[0] + shs[1] + shs[2] + shs[3];
    s2 = sh2[0] + sh2[1] + sh2[2] + sh2[3];
    float mean = s * (1.f/D_);
    float var = s2 * (1.f/D_) - mean*mean;
    float r = rsqrtf(var + 1e-5f);
    float mk = mark[row];
    #pragma unroll
    for (int i = 0; i < 4; i++) {
        int c = tid + i*128;
        float val = (v[i] - mean) * r * g[c] + bt[c];
        out[row*D_ + c] = gelu_f(val) * mk;
    }
}

// ---------------- final classifier GEMV ----------------
__global__ void final_kernel(const float* __restrict__ gfin, const float* __restrict__ pw,
                             const float* __restrict__ pb, float* __restrict__ out)
{
    int idx = blockIdx.x;
    int b = idx / NCLS_, n = idx - b*NCLS_;
    const float* gp = gfin + (long)b*S_*D_;
    const float* wp = pw + (long)n*S_*D_;
    float s = 0.f;
    for (int k = threadIdx.x*4; k < S_*D_; k += 256*4) {
        float4 a  = *(const float4*)(gp + k);
        float4 w4 = *(const float4*)(wp + k);
        s += a.x*w4.x + a.y*w4.y + a.z*w4.z + a.w*w4.w;
    }
    __shared__ float sh[8];
    #pragma unroll
    for (int o = 16; o; o >>= 1) s += __shfl_xor_sync(0xffffffffu, s, o);
    if ((threadIdx.x & 31) == 0) sh[threadIdx.x >> 5] = s;
    __syncthreads();
    if (threadIdx.x == 0) {
        float t = 0.f;
        #pragma unroll
        for (int i = 0; i < 8; i++) t += sh[i];
        out[idx] = t + pb[n];
    }
}

// ---------------- host ----------------
extern "C" void kernel_launch(void* const* d_in, const int* in_sizes, int n_in,
                              void* d_out, int out_size)
{
    const float* x_enc    = (const float*)d_in[0];
    const float* x_mark   = (const float*)d_in[1];
    const float* tok_w    = (const float*)d_in[2];
    const float* Wq       = (const float*)d_in[3];
    const float* bq       = (const float*)d_in[4];
    const float* Wk       = (const float*)d_in[5];
    const float* bk       = (const float*)d_in[6];
    const float* Wv       = (const float*)d_in[7];
    const float* bv       = (const float*)d_in[8];
    const float* Wo       = (const float*)d_in[9];
    const float* bo       = (const float*)d_in[10];
    const float* W1       = (const float*)d_in[11];
    const float* b1       = (const float*)d_in[12];
    const float* W2       = (const float*)d_in[13];
    const float* b2       = (const float*)d_in[14];
    const float* ln1g     = (const float*)d_in[15];
    const float* ln1b     = (const float*)d_in[16];
    const float* ln2g     = (const float*)d_in[17];
    const float* ln2b     = (const float*)d_in[18];
    const float* lnfg     = (const float*)d_in[19];
    const float* lnfb     = (const float*)d_in[20];
    const float* proj_w   = (const float*)d_in[21];
    const float* proj_b   = (const float*)d_in[22];
    const float* tau_conv = (const float*)d_in[23];
    const float* tau_w1   = (const float*)d_in[24];
    const float* tau_b1   = (const float*)d_in[25];
    const float* tau_w2   = (const float*)d_in[26];
    const float* del_conv = (const float*)d_in[27];
    const float* del_w1   = (const float*)d_in[28];
    const float* del_b1   = (const float*)d_in[29];
    const float* del_w2   = (const float*)d_in[30];

    float *px, *pq, *pk, *pv, *po, *ptmp, *pffn, *pattn, *ptau, *pdelta, *pfin;
    cudaGetSymbolAddress((void**)&px,    g_x);
    cudaGetSymbolAddress((void**)&pq,    g_q);
    cudaGetSymbolAddress((void**)&pk,    g_k);
    cudaGetSymbolAddress((void**)&pv,    g_v);
    cudaGetSymbolAddress((void**)&po,    g_o);
    cudaGetSymbolAddress((void**)&ptmp,  g_tmp);
    cudaGetSymbolAddress((void**)&pffn,  g_ffn);
    cudaGetSymbolAddress((void**)&pattn, g_attn);
    cudaGetSymbolAddress((void**)&ptau,  g_tau);
    cudaGetSymbolAddress((void**)&pdelta,g_delta);
    cudaGetSymbolAddress((void**)&pfin,  g_final);

    // dynamic smem: 2 stages of (A 8KB + B NT*64B)
    const int SM128 = 2 * (2048 + 2*16*64) * 4;   // 32768 bytes (NT=128)
    const int SM64  = 2 * (2048 + 2*8*64) * 4;    // 24576 bytes (NT=64)
    cudaFuncSetAttribute(mma_gemm<0,128,false>, cudaFuncAttributeMaxDynamicSharedMemorySize, SM128);
    cudaFuncSetAttribute(mma_gemm<1,128,false>, cudaFuncAttributeMaxDynamicSharedMemorySize, SM128);
    cudaFuncSetAttribute(mma_gemm<2,128,false>, cudaFuncAttributeMaxDynamicSharedMemorySize, SM128);
    cudaFuncSetAttribute(mma_gemm<0,64,true>,   cudaFuncAttributeMaxDynamicSharedMemorySize, SM64);

    proj_kernel<<<B_, 256>>>(x_enc, tau_conv, tau_w1, tau_b1, tau_w2,
                             del_conv, del_w1, del_b1, del_w2);
    embed_kernel<<<B_*S_, 128>>>(x_enc, tok_w);

    const int M = B_*S_;                          // 8192
    dim3 gQKV(M/128, D_/128, 1);                  // (64, 4)
    dim3 gFF1(M/128, DFF_/128, 1);                // (64, 16)
    dim3 gQK(S_/128, S_/128, B_*H_);              // (4, 4, 128)
    dim3 gAV(S_/128, 1, B_*H_);                   // (4, 1, 128)
    const long sBD = (long)S_*D_;
    const long sHSS = (long)H_*S_*S_;
    const long sSS = (long)S_*S_;

    for (int l = 0; l < L_; l++) {
        const float* wq = Wq + (long)l*D_*D_;
        const float* wk = Wk + (long)l*D_*D_;
        const float* wv = Wv + (long)l*D_*D_;
        const float* wo = Wo + (long)l*D_*D_;

        mma_gemm<0,128,false><<<gQKV, 256, SM128>>>(px, D_, 0, 0, wq, D_, 0, 0, bq + l*D_,
                                                    pq, D_, 0, 0, D_, 1, nullptr, nullptr);
        mma_gemm<0,128,false><<<gQKV, 256, SM128>>>(px, D_, 0, 0, wk, D_, 0, 0, bk + l*D_,
                                                    pk, D_, 0, 0, D_, 1, nullptr, nullptr);
        mma_gemm<0,128,false><<<gQKV, 256, SM128>>>(px, D_, 0, 0, wv, D_, 0, 0, bv + l*D_,
                                                    pv, D_, 0, 0, D_, 1, nullptr, nullptr);

        // logits[b,h,l,s] = 0.125 * (q.k * tau[b] + delta[b,s])
        mma_gemm<2,128,false><<<gQK, 256, SM128>>>(pq, D_, sBD, E_, pk, D_, sBD, E_, nullptr,
                                                   pattn, S_, sHSS, sSS, E_, H_, ptau, pdelta);
        softmax_kernel<<<B_*H_*S_, 128>>>(pattn);
        // o = A @ V   (B operand = V accessed transposed)
        mma_gemm<0,64,true><<<gAV, 256, SM64>>>(pattn, S_, sHSS, sSS, pv, D_, sBD, E_, nullptr,
                                                po, D_, sBD, E_, S_, H_, nullptr, nullptr);

        mma_gemm<0,128,false><<<gQKV, 256, SM128>>>(po, D_, 0, 0, wo, D_, 0, 0, bo + l*D_,
                                                    ptmp, D_, 0, 0, D_, 1, nullptr, nullptr);
        add_ln_kernel<<<B_*S_, 128>>>(px, ptmp, ln1g + l*D_, ln1b + l*D_, px);

        mma_gemm<1,128,false><<<gFF1, 256, SM128>>>(px, D_, 0, 0, W1 + (long)l*DFF_*D_, D_, 0, 0,
                                                    b1 + l*DFF_, pffn, DFF_, 0, 0, D_, 1, nullptr, nullptr);
        mma_gemm<0,128,false><<<gQKV, 256, SM128>>>(pffn, DFF_, 0, 0, W2 + (long)l*D_*DFF_, DFF_, 0, 0,
                                                    b2 + l*D_, ptmp, D_, 0, 0, DFF_, 1, nullptr, nullptr);
        add_ln_kernel<<<B_*S_, 128>>>(px, ptmp, ln2g + l*D_, ln2b + l*D_, px);
    }

    lnf_kernel<<<B_*S_, 128>>>(px, lnfg, lnfb, x_mark, pfin);
    final_kernel<<<B_*NCLS_, 256>>>(pfin, proj_w, proj_b, (float*)d_out);
}